// round 16
// baseline (speedup 1.0000x reference)
#include <cuda_runtime.h>
#include <cuda_fp16.h>

#define NMAX 100000
#define EMAX 1600000
#define EPAD (EMAX + 7 * NMAX + 64)
#define ODIM 32
#define KDIM 256
#define ALPHAF 0.2f

// ---------------- scratch (static device globals; no allocation) -------------
__device__ float  g_h[NMAX * ODIM];
__device__ __half g_yA[(NMAX + 1) * ODIM];  // y ping (fp16) + zero row at n
__device__ __half g_yB[(NMAX + 1) * ODIM];  // y pong (fp16) + zero row at n
__device__ int    g_cnt[NMAX];
__device__ float  g_dinv[NMAX];
__device__ float  g_a1[NMAX];               // 0.8 * dinv
__device__ int    g_ptr[NMAX + 1];          // padded CSR offsets
__device__ int    g_cursor[NMAX];
__device__ int    g_idx[EPAD];              // source index per CSR slot
__device__ int    g_bsum[64];
__device__ int    g_boffs[64];

// ---------------- preprocessing kernels --------------------------------------

__global__ void zero_cnt_kernel(int n) {
    int i = blockIdx.x * blockDim.x + threadIdx.x;
    if (i < n) g_cnt[i] = 0;
    if (i < 4) ((uint4*)(g_yA + (size_t)n * ODIM))[i] = make_uint4(0u, 0u, 0u, 0u);
    else if (i < 8) ((uint4*)(g_yB + (size_t)n * ODIM))[i - 4] = make_uint4(0u, 0u, 0u, 0u);
}

// edge_index is INT32 on the wire; col half starts at ei+E. 4 edges/thread.
__global__ void count_kernel(const int* __restrict__ ei, int E) {
    int i = blockIdx.x * blockDim.x + threadIdx.x;
    int Ev = E >> 2;
    if (i < Ev) {
        int4 c = ((const int4*)(ei + E))[i];
        atomicAdd(&g_cnt[c.x], 1);
        atomicAdd(&g_cnt[c.y], 1);
        atomicAdd(&g_cnt[c.z], 1);
        atomicAdd(&g_cnt[c.w], 1);
    }
    int tail = Ev * 4 + i;
    if (i < (E & 3)) atomicAdd(&g_cnt[ei[E + tail]], 1);
}

// --- blocksum (padded counts) + dinv fused ---
__global__ void blocksum_kernel(int n) {
    int base = blockIdx.x * 4096;
    int tid = threadIdx.x;
    int s = 0;
#pragma unroll
    for (int i = 0; i < 8; ++i) {
        int idx = base + tid * 8 + i;
        if (idx < n) {
            int c = g_cnt[idx];
            s += (c + 7) & ~7;                  // padded count
            float d = rsqrtf((float)(c + 1));   // +1 self-loop
            g_dinv[idx] = d;
            g_a1[idx] = (1.0f - ALPHAF) * d;
        }
    }
#pragma unroll
    for (int off = 16; off > 0; off >>= 1)
        s += __shfl_down_sync(0xffffffffu, s, off);
    __shared__ int wsums[16];
    int lane = tid & 31, wid = tid >> 5;
    if (lane == 0) wsums[wid] = s;
    __syncthreads();
    if (wid == 0) {
        int v = (lane < 16) ? wsums[lane] : 0;
#pragma unroll
        for (int off = 16; off > 0; off >>= 1)
            v += __shfl_down_sync(0xffffffffu, v, off);
        if (lane == 0) g_bsum[blockIdx.x] = v;
    }
}

__global__ void scan_bsums_kernel(int nb, int n) {
    int lane = threadIdx.x;
    int carry = 0;
    for (int base = 0; base < nb; base += 32) {
        int v = (base + lane < nb) ? g_bsum[base + lane] : 0;
        int inc = v;
#pragma unroll
        for (int off = 1; off < 32; off <<= 1) {
            int t = __shfl_up_sync(0xffffffffu, inc, off);
            if (lane >= off) inc += t;
        }
        if (base + lane < nb) g_boffs[base + lane] = carry + inc - v;
        carry += __shfl_sync(0xffffffffu, inc, 31);
    }
    if (lane == 0) g_ptr[n] = carry;
}

// scan of padded counts; also writes the pad slots (dummy index n)
__global__ void scan_write_kernel(int n) {
    int base = blockIdx.x * 4096;
    int tid = threadIdx.x;
    int idx0 = base + tid * 8;
    int c[8], v[8], loc[8];
    int run = 0;
#pragma unroll
    for (int i = 0; i < 8; ++i) {
        c[i] = (idx0 + i < n) ? g_cnt[idx0 + i] : 0;
        v[i] = (c[i] + 7) & ~7;                 // padded count
        loc[i] = run;
        run += v[i];
    }
    int lane = tid & 31, wid = tid >> 5;
    int incl = run;
#pragma unroll
    for (int off = 1; off < 32; off <<= 1) {
        int t = __shfl_up_sync(0xffffffffu, incl, off);
        if (lane >= off) incl += t;
    }
    __shared__ int wsums[16];
    if (lane == 31) wsums[wid] = incl;
    __syncthreads();
    if (wid == 0) {
        int x = (lane < 16) ? wsums[lane] : 0;
        int inc = x;
#pragma unroll
        for (int off = 1; off < 32; off <<= 1) {
            int t = __shfl_up_sync(0xffffffffu, inc, off);
            if (lane >= off) inc += t;
        }
        if (lane < 16) wsums[lane] = inc - x;  // exclusive warp offset
    }
    __syncthreads();
    int offset = g_boffs[blockIdx.x] + wsums[wid] + (incl - run);
#pragma unroll
    for (int i = 0; i < 8; ++i)
        if (idx0 + i < n) {
            int o = offset + loc[i];
            g_ptr[idx0 + i] = o;
            g_cursor[idx0 + i] = o;
            for (int p = c[i]; p < v[i]; ++p) g_idx[o + p] = n;
        }
}

__global__ void fill_kernel(const int* __restrict__ ei, int E) {
    int i = blockIdx.x * blockDim.x + threadIdx.x;
    int Ev = E >> 2;
    if (i < Ev) {
        int4 r = ((const int4*)ei)[i];
        int4 c = ((const int4*)(ei + E))[i];
        g_idx[atomicAdd(&g_cursor[c.x], 1)] = r.x;
        g_idx[atomicAdd(&g_cursor[c.y], 1)] = r.y;
        g_idx[atomicAdd(&g_cursor[c.z], 1)] = r.z;
        g_idx[atomicAdd(&g_cursor[c.w], 1)] = r.w;
    }
    int tail = Ev * 4 + i;
    if (i < (E & 3)) {
        int r = ei[tail];
        int c = ei[E + tail];
        g_idx[atomicAdd(&g_cursor[c], 1)] = r;
    }
}

// ---------------- GEMM: h = x @ W^T + b; also y0 = fp16(dinv*h) --------------
__global__ __launch_bounds__(256) void gemm_kernel(
    const float* __restrict__ x, const float* __restrict__ W,
    const float* __restrict__ b, int n) {
    __shared__ float xsf[2][32 * 132];
    __shared__ float wsf[2][32 * 36];
    int tid = threadIdx.x;
    int lane = tid & 31, warp = tid >> 5;
    int ng = warp * 4 + (lane >> 3);
    int og = lane & 7;
    int node0 = blockIdx.x * 128;
    const float4* x4 = (const float4*)x;
    const float4* W4 = (const float4*)W;
    float acc[4][4];
#pragma unroll
    for (int m = 0; m < 4; ++m)
#pragma unroll
        for (int o = 0; o < 4; ++o) acc[m][o] = 0.0f;

    int xrow[4], xkq[4];
#pragma unroll
    for (int i = 0; i < 4; ++i) {
        int f = tid + i * 256;
        xrow[i] = f >> 3;
        xkq[i] = f & 7;
    }
    int wrow = tid >> 3, wkq = tid & 7;

    float4 xreg[4], wreg;
#pragma unroll
    for (int i = 0; i < 4; ++i) {
        xreg[i] = make_float4(0.f, 0.f, 0.f, 0.f);
        if (node0 + xrow[i] < n)
            xreg[i] = x4[(size_t)(node0 + xrow[i]) * 64 + xkq[i]];
    }
    wreg = W4[wrow * 64 + wkq];
#pragma unroll
    for (int i = 0; i < 4; ++i) {
        xsf[0][(xkq[i] * 4 + 0) * 132 + xrow[i]] = xreg[i].x;
        xsf[0][(xkq[i] * 4 + 1) * 132 + xrow[i]] = xreg[i].y;
        xsf[0][(xkq[i] * 4 + 2) * 132 + xrow[i]] = xreg[i].z;
        xsf[0][(xkq[i] * 4 + 3) * 132 + xrow[i]] = xreg[i].w;
    }
    wsf[0][(wkq * 4 + 0) * 36 + wrow] = wreg.x;
    wsf[0][(wkq * 4 + 1) * 36 + wrow] = wreg.y;
    wsf[0][(wkq * 4 + 2) * 36 + wrow] = wreg.z;
    wsf[0][(wkq * 4 + 3) * 36 + wrow] = wreg.w;
    __syncthreads();

#pragma unroll
    for (int t = 0; t < 8; ++t) {
        int cur = t & 1;
        if (t < 7) {
            int kt4 = (t + 1) * 8;
#pragma unroll
            for (int i = 0; i < 4; ++i) {
                xreg[i] = make_float4(0.f, 0.f, 0.f, 0.f);
                if (node0 + xrow[i] < n)
                    xreg[i] = x4[(size_t)(node0 + xrow[i]) * 64 + kt4 + xkq[i]];
            }
            wreg = W4[wrow * 64 + kt4 + wkq];
        }
        const float* xb = xsf[cur];
        const float* wb = wsf[cur];
#pragma unroll
        for (int k = 0; k < 32; ++k) {
            float4 xv = *(const float4*)&xb[k * 132 + ng * 4];
            float4 wv = *(const float4*)&wb[k * 36 + og * 4];
            float xm[4] = {xv.x, xv.y, xv.z, xv.w};
            float wm[4] = {wv.x, wv.y, wv.z, wv.w};
#pragma unroll
            for (int m = 0; m < 4; ++m)
#pragma unroll
                for (int o = 0; o < 4; ++o)
                    acc[m][o] = fmaf(xm[m], wm[o], acc[m][o]);
        }
        if (t < 7) {
            int nxt = cur ^ 1;
#pragma unroll
            for (int i = 0; i < 4; ++i) {
                xsf[nxt][(xkq[i] * 4 + 0) * 132 + xrow[i]] = xreg[i].x;
                xsf[nxt][(xkq[i] * 4 + 1) * 132 + xrow[i]] = xreg[i].y;
                xsf[nxt][(xkq[i] * 4 + 2) * 132 + xrow[i]] = xreg[i].z;
                xsf[nxt][(xkq[i] * 4 + 3) * 132 + xrow[i]] = xreg[i].w;
            }
            wsf[nxt][(wkq * 4 + 0) * 36 + wrow] = wreg.x;
            wsf[nxt][(wkq * 4 + 1) * 36 + wrow] = wreg.y;
            wsf[nxt][(wkq * 4 + 2) * 36 + wrow] = wreg.z;
            wsf[nxt][(wkq * 4 + 3) * 36 + wrow] = wreg.w;
        }
        __syncthreads();
    }

    float4 bv = ((const float4*)b)[og];
#pragma unroll
    for (int m = 0; m < 4; ++m) {
        int node = node0 + ng * 4 + m;
        if (node < n) {
            float d = g_dinv[node];
            float4 hv;
            hv.x = acc[m][0] + bv.x;
            hv.y = acc[m][1] + bv.y;
            hv.z = acc[m][2] + bv.z;
            hv.w = acc[m][3] + bv.w;
            ((float4*)g_h)[(size_t)node * 8 + og] = hv;
            __half2 p0 = __float22half2_rn(make_float2(d * hv.x, d * hv.y));
            __half2 p1 = __float22half2_rn(make_float2(d * hv.z, d * hv.w));
            uint2 pk;
            pk.x = *(unsigned int*)&p0;
            pk.y = *(unsigned int*)&p1;
            ((uint2*)g_yA)[(size_t)node * 8 + og] = pk;
        }
    }
}

// ---------------- propagation: single-wave grid-stride, fp16 gathers ---------
__device__ __forceinline__ void acc8(float* f, uint4 v) {
    __half2 h0 = *(__half2*)&v.x;
    __half2 h1 = *(__half2*)&v.y;
    __half2 h2 = *(__half2*)&v.z;
    __half2 h3 = *(__half2*)&v.w;
    float2 t0 = __half22float2(h0);
    float2 t1 = __half22float2(h1);
    float2 t2 = __half22float2(h2);
    float2 t3 = __half22float2(h3);
    f[0] += t0.x; f[1] += t0.y;
    f[2] += t1.x; f[3] += t1.y;
    f[4] += t2.x; f[5] += t2.y;
    f[6] += t3.x; f[7] += t3.y;
}

__global__ __launch_bounds__(256) void prop_kernel(
    const float* __restrict__ prelu_a, float* __restrict__ out,
    int n, int it) {
    const __half* yin = (it & 1) ? g_yA : g_yB;   // it=1 reads y0 in yA
    int fin = (it == 10);
    __half* yout = (it & 1) ? g_yB : g_yA;

    int lane = threadIdx.x & 31;
    int egrp = lane >> 2;    // edge slot 0..7
    int q = lane & 3;        // uint4 slot within 64B row
    int warp0 = blockIdx.x * 8 + (threadIdx.x >> 5);
    int stride = gridDim.x * 8;
    const uint4* y16 = (const uint4*)yin;

    for (int node = warp0; node < n; node += stride) {
        int s = g_ptr[node];
        int e = g_ptr[node + 1];   // padded: (e-s) % 8 == 0

        float f[8];
#pragma unroll
        for (int j = 0; j < 8; ++j) f[j] = 0.0f;

        int i = s;
        for (; i + 16 <= e; i += 16) {
            int i0 = g_idx[i + egrp];
            int i1 = g_idx[i + 8 + egrp];
            uint4 v0 = y16[(size_t)i0 * 4 + q];
            uint4 v1 = y16[(size_t)i1 * 4 + q];
            acc8(f, v0);
            acc8(f, v1);
        }
        if (i < e) {   // exactly one full 8-edge round
            int i0 = g_idx[i + egrp];
            uint4 v0 = y16[(size_t)i0 * 4 + q];
            acc8(f, v0);
        }
#pragma unroll
        for (int j = 0; j < 8; ++j) {
            f[j] += __shfl_xor_sync(0xffffffffu, f[j], 4);
            f[j] += __shfl_xor_sync(0xffffffffu, f[j], 8);
            f[j] += __shfl_xor_sync(0xffffffffu, f[j], 16);
        }
        if (lane < 4) {
            uint4 sv = y16[(size_t)node * 4 + q];  // self-loop
            acc8(f, sv);
            float a1 = g_a1[node];
            const float4* h4 = (const float4*)g_h;
            float4 h0 = h4[(size_t)node * 8 + q * 2];
            float4 h1 = h4[(size_t)node * 8 + q * 2 + 1];
            float z[8];
            z[0] = fmaf(a1, f[0], ALPHAF * h0.x);
            z[1] = fmaf(a1, f[1], ALPHAF * h0.y);
            z[2] = fmaf(a1, f[2], ALPHAF * h0.z);
            z[3] = fmaf(a1, f[3], ALPHAF * h0.w);
            z[4] = fmaf(a1, f[4], ALPHAF * h1.x);
            z[5] = fmaf(a1, f[5], ALPHAF * h1.y);
            z[6] = fmaf(a1, f[6], ALPHAF * h1.z);
            z[7] = fmaf(a1, f[7], ALPHAF * h1.w);
            if (fin) {
                const float4* pa4 = (const float4*)prelu_a;
                float4 p0 = pa4[q * 2];
                float4 p1 = pa4[q * 2 + 1];
                float4 o0, o1;
                o0.x = (z[0] >= 0.f) ? z[0] : p0.x * z[0];
                o0.y = (z[1] >= 0.f) ? z[1] : p0.y * z[1];
                o0.z = (z[2] >= 0.f) ? z[2] : p0.z * z[2];
                o0.w = (z[3] >= 0.f) ? z[3] : p0.w * z[3];
                o1.x = (z[4] >= 0.f) ? z[4] : p1.x * z[4];
                o1.y = (z[5] >= 0.f) ? z[5] : p1.y * z[5];
                o1.z = (z[6] >= 0.f) ? z[6] : p1.z * z[6];
                o1.w = (z[7] >= 0.f) ? z[7] : p1.w * z[7];
                ((float4*)out)[(size_t)node * 8 + q * 2] = o0;
                ((float4*)out)[(size_t)node * 8 + q * 2 + 1] = o1;
            } else {
                float d = g_dinv[node];
                __half2 p0 = __float22half2_rn(make_float2(d * z[0], d * z[1]));
                __half2 p1 = __float22half2_rn(make_float2(d * z[2], d * z[3]));
                __half2 p2 = __float22half2_rn(make_float2(d * z[4], d * z[5]));
                __half2 p3 = __float22half2_rn(make_float2(d * z[6], d * z[7]));
                uint4 pk;
                pk.x = *(unsigned int*)&p0;
                pk.y = *(unsigned int*)&p1;
                pk.z = *(unsigned int*)&p2;
                pk.w = *(unsigned int*)&p3;
                ((uint4*)yout)[(size_t)node * 4 + q] = pk;
            }
        }
    }
}

// ---------------- launch ------------------------------------------------------
extern "C" void kernel_launch(void* const* d_in, const int* in_sizes, int n_in,
                              void* d_out, int out_size) {
    const float* x = (const float*)d_in[0];
    const int* ei = (const int*)d_in[1];   // int32 edge_index [2, E]
    const float* W = (const float*)d_in[2];
    const float* b = (const float*)d_in[3];
    const float* pa = (const float*)d_in[4];

    int n = in_sizes[0] / KDIM;
    int E = in_sizes[1] / 2;
    int nb = (n + 4095) / 4096;
    int Ev = (E >> 2) + 4;

    // single-wave prop grid: 8 co-resident 256-thread blocks per SM
    int dev = 0, nsm = 148;
    cudaGetDevice(&dev);
    cudaDeviceGetAttribute(&nsm, cudaDevAttrMultiProcessorCount, dev);
    int pgrid = nsm * 8;
    int maxb = (n + 7) / 8;
    if (pgrid > maxb) pgrid = maxb;

    zero_cnt_kernel<<<(n + 255) / 256, 256>>>(n);            // 1
    count_kernel<<<(Ev + 255) / 256, 256>>>(ei, E);          // 2
    blocksum_kernel<<<nb, 512>>>(n);                         // 3
    gemm_kernel<<<(n + 127) / 128, 256>>>(x, W, b, n);       // 4 <- profiled
    scan_bsums_kernel<<<1, 32>>>(nb, n);                     // 5
    scan_write_kernel<<<nb, 512>>>(n);                       // 6 (+pad slots)
    fill_kernel<<<(Ev + 255) / 256, 256>>>(ei, E);           // 7

    for (int it = 1; it <= 10; ++it)
        prop_kernel<<<pgrid, 256>>>(pa, (float*)d_out, n, it);
}

// round 17
// speedup vs baseline: 1.1045x; 1.1045x over previous
#include <cuda_runtime.h>
#include <cuda_fp16.h>

#define NMAX 100000
#define EMAX 1600000
#define ODIM 32
#define KDIM 256
#define ALPHAF 0.2f

// ---------------- scratch (static device globals; no allocation) -------------
__device__ float  g_h[NMAX * ODIM];
__device__ __half g_yA[(NMAX + 1) * ODIM];  // y ping (fp16)
__device__ __half g_yB[(NMAX + 1) * ODIM];  // y pong (fp16)
__device__ int    g_cnt[NMAX];
__device__ float  g_dinv[NMAX];
__device__ float  g_a1[NMAX];               // 0.8 * dinv
__device__ int    g_ptr[NMAX + 1];
__device__ int    g_cursor[NMAX];
__device__ int    g_idx[EMAX + 16];         // source index per CSR slot
__device__ int    g_bsum[64];
__device__ int    g_boffs[64];

// ---------------- preprocessing kernels --------------------------------------

__global__ void zero_cnt_kernel(int n) {
    int i = blockIdx.x * blockDim.x + threadIdx.x;
    if (i < n) g_cnt[i] = 0;
}

// edge_index is INT32 on the wire; col half starts at ei+E. 4 edges/thread.
__global__ void count_kernel(const int* __restrict__ ei, int E) {
    int i = blockIdx.x * blockDim.x + threadIdx.x;
    int Ev = E >> 2;
    if (i < Ev) {
        int4 c = ((const int4*)(ei + E))[i];
        atomicAdd(&g_cnt[c.x], 1);
        atomicAdd(&g_cnt[c.y], 1);
        atomicAdd(&g_cnt[c.z], 1);
        atomicAdd(&g_cnt[c.w], 1);
    }
    int tail = Ev * 4 + i;
    if (i < (E & 3)) atomicAdd(&g_cnt[ei[E + tail]], 1);
}

// --- blocksum + dinv fused (both read g_cnt) ---
__global__ void blocksum_kernel(int n) {
    int base = blockIdx.x * 4096;
    int tid = threadIdx.x;
    int s = 0;
#pragma unroll
    for (int i = 0; i < 8; ++i) {
        int idx = base + tid * 8 + i;
        if (idx < n) {
            int c = g_cnt[idx];
            s += c;
            float d = rsqrtf((float)(c + 1));   // +1 self-loop
            g_dinv[idx] = d;
            g_a1[idx] = (1.0f - ALPHAF) * d;
        }
    }
#pragma unroll
    for (int off = 16; off > 0; off >>= 1)
        s += __shfl_down_sync(0xffffffffu, s, off);
    __shared__ int wsums[16];
    int lane = tid & 31, wid = tid >> 5;
    if (lane == 0) wsums[wid] = s;
    __syncthreads();
    if (wid == 0) {
        int v = (lane < 16) ? wsums[lane] : 0;
#pragma unroll
        for (int off = 16; off > 0; off >>= 1)
            v += __shfl_down_sync(0xffffffffu, v, off);
        if (lane == 0) g_bsum[blockIdx.x] = v;
    }
}

__global__ void scan_bsums_kernel(int nb, int n) {
    int lane = threadIdx.x;
    int carry = 0;
    for (int base = 0; base < nb; base += 32) {
        int v = (base + lane < nb) ? g_bsum[base + lane] : 0;
        int inc = v;
#pragma unroll
        for (int off = 1; off < 32; off <<= 1) {
            int t = __shfl_up_sync(0xffffffffu, inc, off);
            if (lane >= off) inc += t;
        }
        if (base + lane < nb) g_boffs[base + lane] = carry + inc - v;
        carry += __shfl_sync(0xffffffffu, inc, 31);
    }
    if (lane == 0) g_ptr[n] = carry;
}

__global__ void scan_write_kernel(int n) {
    int base = blockIdx.x * 4096;
    int tid = threadIdx.x;
    int idx0 = base + tid * 8;
    int v[8], loc[8];
    int run = 0;
#pragma unroll
    for (int i = 0; i < 8; ++i) {
        v[i] = (idx0 + i < n) ? g_cnt[idx0 + i] : 0;
        loc[i] = run;
        run += v[i];
    }
    int lane = tid & 31, wid = tid >> 5;
    int incl = run;
#pragma unroll
    for (int off = 1; off < 32; off <<= 1) {
        int t = __shfl_up_sync(0xffffffffu, incl, off);
        if (lane >= off) incl += t;
    }
    __shared__ int wsums[16];
    if (lane == 31) wsums[wid] = incl;
    __syncthreads();
    if (wid == 0) {
        int x = (lane < 16) ? wsums[lane] : 0;
        int inc = x;
#pragma unroll
        for (int off = 1; off < 32; off <<= 1) {
            int t = __shfl_up_sync(0xffffffffu, inc, off);
            if (lane >= off) inc += t;
        }
        if (lane < 16) wsums[lane] = inc - x;  // exclusive warp offset
    }
    __syncthreads();
    int offset = g_boffs[blockIdx.x] + wsums[wid] + (incl - run);
#pragma unroll
    for (int i = 0; i < 8; ++i)
        if (idx0 + i < n) {
            g_ptr[idx0 + i] = offset + loc[i];
            g_cursor[idx0 + i] = offset + loc[i];
        }
}

__global__ void fill_kernel(const int* __restrict__ ei, int E) {
    int i = blockIdx.x * blockDim.x + threadIdx.x;
    int Ev = E >> 2;
    if (i < Ev) {
        int4 r = ((const int4*)ei)[i];
        int4 c = ((const int4*)(ei + E))[i];
        g_idx[atomicAdd(&g_cursor[c.x], 1)] = r.x;
        g_idx[atomicAdd(&g_cursor[c.y], 1)] = r.y;
        g_idx[atomicAdd(&g_cursor[c.z], 1)] = r.z;
        g_idx[atomicAdd(&g_cursor[c.w], 1)] = r.w;
    }
    int tail = Ev * 4 + i;
    if (i < (E & 3)) {
        int r = ei[tail];
        int c = ei[E + tail];
        g_idx[atomicAdd(&g_cursor[c], 1)] = r;
    }
}

// ---------------- GEMM: h = x @ W^T + b; also y0 = fp16(dinv*h) --------------
__global__ __launch_bounds__(256) void gemm_kernel(
    const float* __restrict__ x, const float* __restrict__ W,
    const float* __restrict__ b, int n) {
    __shared__ float xsf[2][32 * 132];
    __shared__ float wsf[2][32 * 36];
    int tid = threadIdx.x;
    int lane = tid & 31, warp = tid >> 5;
    int ng = warp * 4 + (lane >> 3);
    int og = lane & 7;
    int node0 = blockIdx.x * 128;
    const float4* x4 = (const float4*)x;
    const float4* W4 = (const float4*)W;
    float acc[4][4];
#pragma unroll
    for (int m = 0; m < 4; ++m)
#pragma unroll
        for (int o = 0; o < 4; ++o) acc[m][o] = 0.0f;

    int xrow[4], xkq[4];
#pragma unroll
    for (int i = 0; i < 4; ++i) {
        int f = tid + i * 256;
        xrow[i] = f >> 3;
        xkq[i] = f & 7;
    }
    int wrow = tid >> 3, wkq = tid & 7;

    float4 xreg[4], wreg;
#pragma unroll
    for (int i = 0; i < 4; ++i) {
        xreg[i] = make_float4(0.f, 0.f, 0.f, 0.f);
        if (node0 + xrow[i] < n)
            xreg[i] = x4[(size_t)(node0 + xrow[i]) * 64 + xkq[i]];
    }
    wreg = W4[wrow * 64 + wkq];
#pragma unroll
    for (int i = 0; i < 4; ++i) {
        xsf[0][(xkq[i] * 4 + 0) * 132 + xrow[i]] = xreg[i].x;
        xsf[0][(xkq[i] * 4 + 1) * 132 + xrow[i]] = xreg[i].y;
        xsf[0][(xkq[i] * 4 + 2) * 132 + xrow[i]] = xreg[i].z;
        xsf[0][(xkq[i] * 4 + 3) * 132 + xrow[i]] = xreg[i].w;
    }
    wsf[0][(wkq * 4 + 0) * 36 + wrow] = wreg.x;
    wsf[0][(wkq * 4 + 1) * 36 + wrow] = wreg.y;
    wsf[0][(wkq * 4 + 2) * 36 + wrow] = wreg.z;
    wsf[0][(wkq * 4 + 3) * 36 + wrow] = wreg.w;
    __syncthreads();

#pragma unroll
    for (int t = 0; t < 8; ++t) {
        int cur = t & 1;
        if (t < 7) {
            int kt4 = (t + 1) * 8;
#pragma unroll
            for (int i = 0; i < 4; ++i) {
                xreg[i] = make_float4(0.f, 0.f, 0.f, 0.f);
                if (node0 + xrow[i] < n)
                    xreg[i] = x4[(size_t)(node0 + xrow[i]) * 64 + kt4 + xkq[i]];
            }
            wreg = W4[wrow * 64 + kt4 + wkq];
        }
        const float* xb = xsf[cur];
        const float* wb = wsf[cur];
#pragma unroll
        for (int k = 0; k < 32; ++k) {
            float4 xv = *(const float4*)&xb[k * 132 + ng * 4];
            float4 wv = *(const float4*)&wb[k * 36 + og * 4];
            float xm[4] = {xv.x, xv.y, xv.z, xv.w};
            float wm[4] = {wv.x, wv.y, wv.z, wv.w};
#pragma unroll
            for (int m = 0; m < 4; ++m)
#pragma unroll
                for (int o = 0; o < 4; ++o)
                    acc[m][o] = fmaf(xm[m], wm[o], acc[m][o]);
        }
        if (t < 7) {
            int nxt = cur ^ 1;
#pragma unroll
            for (int i = 0; i < 4; ++i) {
                xsf[nxt][(xkq[i] * 4 + 0) * 132 + xrow[i]] = xreg[i].x;
                xsf[nxt][(xkq[i] * 4 + 1) * 132 + xrow[i]] = xreg[i].y;
                xsf[nxt][(xkq[i] * 4 + 2) * 132 + xrow[i]] = xreg[i].z;
                xsf[nxt][(xkq[i] * 4 + 3) * 132 + xrow[i]] = xreg[i].w;
            }
            wsf[nxt][(wkq * 4 + 0) * 36 + wrow] = wreg.x;
            wsf[nxt][(wkq * 4 + 1) * 36 + wrow] = wreg.y;
            wsf[nxt][(wkq * 4 + 2) * 36 + wrow] = wreg.z;
            wsf[nxt][(wkq * 4 + 3) * 36 + wrow] = wreg.w;
        }
        __syncthreads();
    }

    float4 bv = ((const float4*)b)[og];
#pragma unroll
    for (int m = 0; m < 4; ++m) {
        int node = node0 + ng * 4 + m;
        if (node < n) {
            float d = g_dinv[node];
            float4 hv;
            hv.x = acc[m][0] + bv.x;
            hv.y = acc[m][1] + bv.y;
            hv.z = acc[m][2] + bv.z;
            hv.w = acc[m][3] + bv.w;
            ((float4*)g_h)[(size_t)node * 8 + og] = hv;
            __half2 p0 = __float22half2_rn(make_float2(d * hv.x, d * hv.y));
            __half2 p1 = __float22half2_rn(make_float2(d * hv.z, d * hv.w));
            uint2 pk;
            pk.x = *(unsigned int*)&p0;
            pk.y = *(unsigned int*)&p1;
            ((uint2*)g_yA)[(size_t)node * 8 + og] = pk;
        }
    }
}

// ---------------- propagation: warp per node, fp16 gathers, 128-thr blocks ---
__device__ __forceinline__ void acc8(float* f, uint4 v) {
    __half2 h0 = *(__half2*)&v.x;
    __half2 h1 = *(__half2*)&v.y;
    __half2 h2 = *(__half2*)&v.z;
    __half2 h3 = *(__half2*)&v.w;
    float2 t0 = __half22float2(h0);
    float2 t1 = __half22float2(h1);
    float2 t2 = __half22float2(h2);
    float2 t3 = __half22float2(h3);
    f[0] += t0.x; f[1] += t0.y;
    f[2] += t1.x; f[3] += t1.y;
    f[4] += t2.x; f[5] += t2.y;
    f[6] += t3.x; f[7] += t3.y;
}

__global__ __launch_bounds__(128) void prop_kernel(
    const float* __restrict__ prelu_a, float* __restrict__ out,
    int n, int it) {
    const __half* yin = (it & 1) ? g_yA : g_yB;   // it=1 reads y0 in yA
    int fin = (it == 10);
    __half* yout = (it & 1) ? g_yB : g_yA;

    int node = blockIdx.x * 4 + (threadIdx.x >> 5);
    if (node >= n) return;
    int lane = threadIdx.x & 31;
    int egrp = lane >> 2;    // edge slot 0..7
    int q = lane & 3;        // uint4 slot within 64B row

    int s = g_ptr[node];
    int e = g_ptr[node + 1];
    const uint4* y16 = (const uint4*)yin;

    float f[8];
#pragma unroll
    for (int j = 0; j < 8; ++j) f[j] = 0.0f;

    int i = s;
    for (; i + 16 <= e; i += 16) {
        int i0 = g_idx[i + egrp];
        int i1 = g_idx[i + 8 + egrp];
        uint4 v0 = y16[(size_t)i0 * 4 + q];
        uint4 v1 = y16[(size_t)i1 * 4 + q];
        acc8(f, v0);
        acc8(f, v1);
    }
    // masked tail rounds (<=2): inactive slots contribute +0
    for (; i < e; i += 8) {
        uint4 v = make_uint4(0u, 0u, 0u, 0u);
        if (i + egrp < e) {
            int idx = g_idx[i + egrp];
            v = y16[(size_t)idx * 4 + q];
        }
        acc8(f, v);
    }
#pragma unroll
    for (int j = 0; j < 8; ++j) {
        f[j] += __shfl_xor_sync(0xffffffffu, f[j], 4);
        f[j] += __shfl_xor_sync(0xffffffffu, f[j], 8);
        f[j] += __shfl_xor_sync(0xffffffffu, f[j], 16);
    }
    if (lane < 4) {
        uint4 sv = y16[(size_t)node * 4 + q];  // self-loop
        acc8(f, sv);
        float a1 = g_a1[node];
        const float4* h4 = (const float4*)g_h;
        float4 h0 = h4[(size_t)node * 8 + q * 2];
        float4 h1 = h4[(size_t)node * 8 + q * 2 + 1];
        float z[8];
        z[0] = fmaf(a1, f[0], ALPHAF * h0.x);
        z[1] = fmaf(a1, f[1], ALPHAF * h0.y);
        z[2] = fmaf(a1, f[2], ALPHAF * h0.z);
        z[3] = fmaf(a1, f[3], ALPHAF * h0.w);
        z[4] = fmaf(a1, f[4], ALPHAF * h1.x);
        z[5] = fmaf(a1, f[5], ALPHAF * h1.y);
        z[6] = fmaf(a1, f[6], ALPHAF * h1.z);
        z[7] = fmaf(a1, f[7], ALPHAF * h1.w);
        if (fin) {
            const float4* pa4 = (const float4*)prelu_a;
            float4 p0 = pa4[q * 2];
            float4 p1 = pa4[q * 2 + 1];
            float4 o0, o1;
            o0.x = (z[0] >= 0.f) ? z[0] : p0.x * z[0];
            o0.y = (z[1] >= 0.f) ? z[1] : p0.y * z[1];
            o0.z = (z[2] >= 0.f) ? z[2] : p0.z * z[2];
            o0.w = (z[3] >= 0.f) ? z[3] : p0.w * z[3];
            o1.x = (z[4] >= 0.f) ? z[4] : p1.x * z[4];
            o1.y = (z[5] >= 0.f) ? z[5] : p1.y * z[5];
            o1.z = (z[6] >= 0.f) ? z[6] : p1.z * z[6];
            o1.w = (z[7] >= 0.f) ? z[7] : p1.w * z[7];
            ((float4*)out)[(size_t)node * 8 + q * 2] = o0;
            ((float4*)out)[(size_t)node * 8 + q * 2 + 1] = o1;
        } else {
            float d = g_dinv[node];
            __half2 p0 = __float22half2_rn(make_float2(d * z[0], d * z[1]));
            __half2 p1 = __float22half2_rn(make_float2(d * z[2], d * z[3]));
            __half2 p2 = __float22half2_rn(make_float2(d * z[4], d * z[5]));
            __half2 p3 = __float22half2_rn(make_float2(d * z[6], d * z[7]));
            uint4 pk;
            pk.x = *(unsigned int*)&p0;
            pk.y = *(unsigned int*)&p1;
            pk.z = *(unsigned int*)&p2;
            pk.w = *(unsigned int*)&p3;
            ((uint4*)yout)[(size_t)node * 4 + q] = pk;
        }
    }
}

// ---------------- launch ------------------------------------------------------
extern "C" void kernel_launch(void* const* d_in, const int* in_sizes, int n_in,
                              void* d_out, int out_size) {
    const float* x = (const float*)d_in[0];
    const int* ei = (const int*)d_in[1];   // int32 edge_index [2, E]
    const float* W = (const float*)d_in[2];
    const float* b = (const float*)d_in[3];
    const float* pa = (const float*)d_in[4];

    int n = in_sizes[0] / KDIM;
    int E = in_sizes[1] / 2;
    int nb = (n + 4095) / 4096;
    int Ev = (E >> 2) + 4;

    zero_cnt_kernel<<<(n + 255) / 256, 256>>>(n);            // 1
    count_kernel<<<(Ev + 255) / 256, 256>>>(ei, E);          // 2
    blocksum_kernel<<<nb, 512>>>(n);                         // 3
    gemm_kernel<<<(n + 127) / 128, 256>>>(x, W, b, n);       // 4 <- profiled
    scan_bsums_kernel<<<1, 32>>>(nb, n);                     // 5
    scan_write_kernel<<<nb, 512>>>(n);                       // 6
    fill_kernel<<<(Ev + 255) / 256, 256>>>(ei, E);           // 7

    for (int it = 1; it <= 10; ++it)
        prop_kernel<<<(n + 3) / 4, 128>>>(pa, (float*)d_out, n, it);
}